// round 14
// baseline (speedup 1.0000x reference)
#include <cuda_runtime.h>
#include <cuda_bf16.h>
#include <cstdint>

// LinearMimo via warp-level tensor cores (mma.sync), single fused launch.
// IIR (|poles| <= ~0.49) truncated to a 16-tap FIR (error ~1e-5).
// y[b,t,o] = sum_{d<16,i} h[o,i,d] u[b,t-d,i]  ==  per-128-t-tile GEMM
// D(128x8) = sum_{s=0..7} A_s(128x16) x B_s(16x8), K = 2 taps x 8 i.
// A_s rows = 16 consecutive bf16 of the staged u tile at 16B row offsets
// (windows contiguous in (T,I) layout -> no im2col). Precision: bf16 2-way
// split of u and h, 3 MMA products, fp32 accumulators -> ~5e-6 rel err.
// ONE kernel: blockIdx.x<64 = GEMM blocks (each recomputes B fragments
// locally, ~150 cyc); blockIdx.x==64 = exact first-128-steps block (y_0,u_0),
// running concurrently.

#define Bb 32
#define Tt 16384
#define NT 16            // FIR taps
#define NS 8             // tap-pairs = K16 MMA steps
#define AROWS 144        // 143 rows used: u[t0-15 .. t0+127]

static __device__ __forceinline__ uint32_t smem_u32(const void* p) {
    uint32_t a;
    asm("{.reg .u64 t; cvta.to.shared.u64 t, %1; cvt.u32.u64 %0, t;}" : "=r"(a) : "l"(p));
    return a;
}

#define MMA16816(C, A0, A1, A2, A3, B0, B1)                                  \
    asm volatile(                                                            \
        "mma.sync.aligned.m16n8k16.row.col.f32.bf16.bf16.f32 "               \
        "{%0,%1,%2,%3}, {%4,%5,%6,%7}, {%8,%9}, {%0,%1,%2,%3};"              \
        : "+f"((C)[0]), "+f"((C)[1]), "+f"((C)[2]), "+f"((C)[3])             \
        : "r"(A0), "r"(A1), "r"(A2), "r"(A3), "r"(B0), "r"(B1));

#define LDSM4(R0, R1, R2, R3, ADDR)                                          \
    asm volatile("ldmatrix.sync.aligned.m8n8.x4.shared.b16 {%0,%1,%2,%3}, [%4];" \
                 : "=r"(R0), "=r"(R1), "=r"(R2), "=r"(R3) : "r"(ADDR));

// ---- scalar IIR step macros (exact-head path) ----
#define STEP2S(UA, UB, PS)                                                   \
    {                                                                        \
        float firA_ = fmaf(cb2x, u2x, fmaf(cb1x, u1x, cb0x * (UA)));         \
        float xnA_ = fmaf(na0x, x1x, fmaf(na1x, x2x, firA_));                \
        x2x = x1x; x1x = xnA_; u2x = u1x; u1x = (UA);                        \
        float firB_ = fmaf(cb2y, u2y, fmaf(cb1y, u1y, cb0y * (UB)));         \
        float xnB_ = fmaf(na0y, x1y, fmaf(na1y, x2y, firB_));                \
        x2y = x1y; x1y = xnB_; u2y = u1y; u1y = (UB);                        \
        PS = xnA_ + xnB_;                                                    \
    }
#define STEP2N(UA, UB)                                                       \
    {                                                                        \
        float firA_ = fmaf(cb2x, u2x, fmaf(cb1x, u1x, cb0x * (UA)));         \
        float xnA_ = fmaf(na0x, x1x, fmaf(na1x, x2x, firA_));                \
        x2x = x1x; x1x = xnA_; u2x = u1x; u1x = (UA);                        \
        float firB_ = fmaf(cb2y, u2y, fmaf(cb1y, u1y, cb0y * (UB)));         \
        float xnB_ = fmaf(na0y, x1y, fmaf(na1y, x2y, firB_));                \
        x2y = x1y; x1y = xnB_; u2y = u1y; u1y = (UB);                        \
    }

struct __align__(16) FSmem {
    float hh[64][NT];                // fp32 hi-split taps per (o*8+i)
    float hl[64][NT];                // residual taps
    __nv_bfloat16 ahi[AROWS * 8];    // A tile hi split: row j <-> u[t0-15+j]
    __nv_bfloat16 alo[AROWS * 8];
};

__global__ void __launch_bounds__(128) fused_kernel(
    const float* __restrict__ bc, const float* __restrict__ ac,
    const float* __restrict__ u_in, const float* __restrict__ y0,
    const float* __restrict__ u0, float* __restrict__ y)
{
    const int b = blockIdx.y;
    const int bx = blockIdx.x;
    const int tid = threadIdx.x;

    // ================= exact-head block (t = 0..127, exact ICs) ============
    if (bx == 64) {
        const int o = tid & 7, iq = (tid >> 3) & 3, cb = tid >> 5;
        __shared__ __align__(16) float us[4 * 416];   // 4 chunks x 4 planes x 104

        const float* bq = bc + o * 24 + iq * 6;
        const float cb0x = bq[0], cb1x = bq[1], cb2x = bq[2];
        const float cb0y = bq[3], cb1y = bq[4], cb2y = bq[5];
        const float4 av = *(const float4*)(ac + o * 16 + iq * 4);
        const float na0x = -av.x, na1x = -av.y, na0y = -av.z, na1y = -av.w;

        // tile: slot r <-> t = c*32 - 18 + r (50 slots per chunk)
#pragma unroll
        for (int c = 0; c < 4; c++) {
            float* dst = us + c * 416;
            const int lo = (c == 0) ? 36 : 0;
            const float4* src = (const float4*)u_in +
                ((c == 0) ? (size_t)b * Tt * 2 : ((size_t)b * Tt + c * 32 - 18) * 2) - lo;
            if (tid >= lo && tid < 100) {
                const float4 v = src[tid];
                const int ts = tid >> 1, h = tid & 1;
                float* p0 = dst + (2 * h) * 104 + ts * 2;
                p0[0] = v.x; p0[1] = v.y; p0[104] = v.z; p0[105] = v.w;
            }
        }
        if (tid < 16) {
            const int r = 16 + (tid >> 3), ii = tid & 7;
            // u_0[...,k] = u[-1-k]: slot 17 -> u[-1] (k=0), slot 16 -> u[-2] (k=1)
            us[(ii >> 1) * 104 + r * 2 + (ii & 1)] = u0[(b * 8 + ii) * 3 + (17 - r)];
        }
        __syncthreads();

        const float* upq = us + cb * 416 + iq * 104;
        float x1x, x2x, u1x, u2x, x1y, x2y, u1y, u2y;
        if (cb == 0) {
            const float4 v = *(const float4*)(y0 + (b * 8 + o) * 16 + iq * 4);
            x1x = v.x; x2x = v.y; x1y = v.z; x2y = v.w;      // x[-1], x[-2]
            const float4 w = *(const float4*)(upq + 16 * 2); // slots 16,17
            u2x = w.x; u2y = w.y; u1x = w.z; u1y = w.w;      // u[-2], u[-1]
        } else {
            x1x = x2x = x1y = x2y = 0.f;
            const float4 w = *(const float4*)(upq);          // slots 0,1
            u2x = w.x; u2y = w.y; u1x = w.z; u1y = w.w;
#pragma unroll
            for (int r = 2; r < 18; r += 2) {                // 16-step warm-up
                const float4 v = *(const float4*)(upq + r * 2);
                STEP2N(v.x, v.y) STEP2N(v.z, v.w)
            }
        }

        float* yp = y + ((size_t)b * Tt + cb * 32) * 8 + o;
        const bool hi1 = (iq & 2) != 0, hi0 = (iq & 1) != 0;
#pragma unroll
        for (int s = 0; s < 32; s += 4) {
            float ps0, ps1, ps2, ps3;
            const float4 va = *(const float4*)(upq + (18 + s) * 2);
            STEP2S(va.x, va.y, ps0)
            STEP2S(va.z, va.w, ps1)
            const float4 vb = *(const float4*)(upq + (20 + s) * 2);
            STEP2S(vb.x, vb.y, ps2)
            STEP2S(vb.z, vb.w, ps3)
            const float sA0 = hi1 ? ps0 : ps2;
            const float sA1 = hi1 ? ps1 : ps3;
            const float rA0 = __shfl_xor_sync(0xffffffffu, sA0, 16);
            const float rA1 = __shfl_xor_sync(0xffffffffu, sA1, 16);
            const float w0 = (hi1 ? ps2 : ps0) + rA0;
            const float w1 = (hi1 ? ps3 : ps1) + rA1;
            const float sB = hi0 ? w0 : w1;
            const float rB = __shfl_xor_sync(0xffffffffu, sB, 8);
            const float mine = hi0 ? w1 : w0;
            yp[(size_t)(s + iq) * 8] = mine + rB;
        }
        return;
    }

    // ================= GEMM blocks: tiles t_idx = 1 + bx*2 + {0,1} =========
    __shared__ FSmem sm;
    const int wid = tid >> 5, lid = tid & 31;
    const int tc = lid & 3, g = lid >> 2;

    // ---- local B-fragment build: 64 threads run the 16-step tap recurrence
    if (tid < 64) {
        const float b0 = bc[tid * 3 + 0], b1c = bc[tid * 3 + 1], b2 = bc[tid * 3 + 2];
        const float a0 = ac[tid * 2 + 0], a1 = ac[tid * 2 + 1];
        float h1 = 0.f, h2 = 0.f;
#pragma unroll
        for (int d = 0; d < NT; d++) {
            const float f = (d == 0) ? b0 : (d == 1) ? b1c : (d == 2) ? b2 : 0.f;
            const float h = f - a0 * h1 - a1 * h2;
            const float hhv = __bfloat162float(__float2bfloat16(h));
            sm.hh[tid][d] = hhv;
            sm.hl[tid][d] = h - hhv;
            h2 = h1; h1 = h;
        }
    }
    __syncthreads();

    // every thread gathers its per-lane fragments (same for all 4 warps)
    uint32_t bh0[NS], bh1[NS], bl0[NS], bl1[NS];
#pragma unroll
    for (int s = 0; s < NS; s++) {
        float vh[4], vl[4];
#pragma unroll
        for (int e = 0; e < 4; e++) {
            const int kk = 2 * tc + (e & 1) + ((e >> 1) ? 8 : 0);
            const int i = (kk < 8) ? kk : kk - 8;
            const int d = (kk < 8) ? 2 * s + 1 : 2 * s;
            vh[e] = sm.hh[g * 8 + i][d];
            vl[e] = sm.hl[g * 8 + i][d];
        }
        __nv_bfloat162 p0 = __halves2bfloat162(__float2bfloat16(vh[0]), __float2bfloat16(vh[1]));
        __nv_bfloat162 p1 = __halves2bfloat162(__float2bfloat16(vh[2]), __float2bfloat16(vh[3]));
        __nv_bfloat162 q0 = __halves2bfloat162(__float2bfloat16(vl[0]), __float2bfloat16(vl[1]));
        __nv_bfloat162 q1 = __halves2bfloat162(__float2bfloat16(vl[2]), __float2bfloat16(vl[3]));
        bh0[s] = *(uint32_t*)&p0; bh1[s] = *(uint32_t*)&p1;
        bl0[s] = *(uint32_t*)&q0; bl1[s] = *(uint32_t*)&q1;
    }

    const uint32_t ahi_u = smem_u32(sm.ahi);
    const uint32_t alo_u = smem_u32(sm.alo);
    // ldmatrix lane address: lanes 0-15 -> rows 0-15 (k 0-7), 16-31 -> +1 row
    const uint32_t rowoff = (uint32_t)(((lid & 15) + (lid >> 4)) * 16);

#pragma unroll
    for (int k = 0; k < 2; k++) {
        const int t_idx = 1 + bx * 2 + k;       // 1..128; 128 masked
        const bool active = (t_idx <= 127);
        if (active) {
            const int t0 = t_idx * 128;
            const float4* src = (const float4*)u_in + ((size_t)b * Tt + t0 - 15) * 2;
            for (int q = tid; q < 143 * 2; q += 128) {
                const float4 v = src[q];
                const __nv_bfloat16 h0 = __float2bfloat16(v.x);
                const __nv_bfloat16 h1 = __float2bfloat16(v.y);
                const __nv_bfloat16 h2 = __float2bfloat16(v.z);
                const __nv_bfloat16 h3 = __float2bfloat16(v.w);
                const __nv_bfloat16 l0 = __float2bfloat16(v.x - __bfloat162float(h0));
                const __nv_bfloat16 l1 = __float2bfloat16(v.y - __bfloat162float(h1));
                const __nv_bfloat16 l2 = __float2bfloat16(v.z - __bfloat162float(h2));
                const __nv_bfloat16 l3 = __float2bfloat16(v.w - __bfloat162float(h3));
                __nv_bfloat162* dh = (__nv_bfloat162*)sm.ahi + q * 2;
                dh[0] = __halves2bfloat162(h0, h1);
                dh[1] = __halves2bfloat162(h2, h3);
                __nv_bfloat162* dl = (__nv_bfloat162*)sm.alo + q * 2;
                dl[0] = __halves2bfloat162(l0, l1);
                dl[1] = __halves2bfloat162(l2, l3);
            }
        }
        __syncthreads();
        if (active) {
            float acc[2][4];
#pragma unroll
            for (int m = 0; m < 2; m++)
#pragma unroll
                for (int e = 0; e < 4; e++) acc[m][e] = 0.f;
#pragma unroll
            for (int s = 0; s < NS; s++) {
#pragma unroll
                for (int m = 0; m < 2; m++) {
                    const int mt = wid * 2 + m;
                    // A_s row t: k0-7 = u[t0+t-2s-1] -> smem row j = t + 14 - 2s
                    const uint32_t base = (uint32_t)((mt * 16 + 14 - 2 * s) * 16) + rowoff;
                    uint32_t ah0, ah1, ah2, ah3, al0r, al1r, al2r, al3r;
                    LDSM4(ah0, ah1, ah2, ah3, ahi_u + base)
                    LDSM4(al0r, al1r, al2r, al3r, alo_u + base)
                    MMA16816(acc[m], ah0, ah1, ah2, ah3, bh0[s], bh1[s])
                    MMA16816(acc[m], al0r, al1r, al2r, al3r, bh0[s], bh1[s])
                    MMA16816(acc[m], ah0, ah1, ah2, ah3, bl0[s], bl1[s])
                }
            }
            const int t0 = t_idx * 128;
#pragma unroll
            for (int m = 0; m < 2; m++) {
                const int mt = wid * 2 + m;
                float* dst = y + ((size_t)b * Tt + t0 + mt * 16 + g) * 8 + 2 * tc;
                *(float2*)dst = make_float2(acc[m][0], acc[m][1]);
                *(float2*)(dst + 64) = make_float2(acc[m][2], acc[m][3]);  // row g+8
            }
        }
        __syncthreads();
    }
}

extern "C" void kernel_launch(void* const* d_in, const int* in_sizes, int n_in,
                              void* d_out, int out_size) {
    const float* bc = (const float*)d_in[0];  // b_coeff (O,I,3)
    const float* ac = (const float*)d_in[1];  // a_coeff (O,I,2)
    const float* u  = (const float*)d_in[2];  // u_in    (B,T,I)
    const float* y0 = (const float*)d_in[3];  // y_0     (B,O,I,2)
    const float* u0 = (const float*)d_in[4];  // u_0     (B,I,3)
    float* y = (float*)d_out;                 // (B,T,O)

    fused_kernel<<<dim3(65, Bb), 128>>>(bc, ac, u, y0, u0, y);
}

// round 15
// speedup vs baseline: 2.0579x; 2.0579x over previous
#include <cuda_runtime.h>
#include <cuda_bf16.h>
#include <cstdint>

// LinearMimo via warp-level tensor cores (mma.sync), single fused launch.
// IIR (|poles| <= ~0.49) truncated to a 16-tap FIR (error ~1e-5).
// y[b,t,o] = sum_{d<16,i} h[o,i,d] u[b,t-d,i]  ==  per-128-t-tile GEMM
// D(128x8) = sum_{s=0..7} A_s(128x16) x B_s(16x8), K = 2 taps x 8 i.
// A_s rows = 16 consecutive bf16 of the staged u tile at 16B row offsets.
// Precision: bf16 2-way split of u and h, 3 MMA products, fp32 accum (~5e-6).
// B fragments are built PER-LANE IN REGISTERS: lane (g,tc) needs taps only for
// filters (o=g, i=2tc) and (o=g, i=2tc+1) -> it runs those two 16-step tap
// recurrences itself (no smem, no bank conflicts -- the R13 fusion regression
// was a 32-way-conflicted smem gather).
// blockIdx.x<64: GEMM blocks (2 tiles each); blockIdx.x==64: exact first-128
// steps with true ICs (y_0, u_0), concurrent.

#define Bb 32
#define Tt 16384
#define NT 16            // FIR taps
#define NS 8             // tap-pairs = K16 MMA steps
#define AROWS 144        // 143 rows used: u[t0-15 .. t0+127]

static __device__ __forceinline__ uint32_t smem_u32(const void* p) {
    uint32_t a;
    asm("{.reg .u64 t; cvta.to.shared.u64 t, %1; cvt.u32.u64 %0, t;}" : "=r"(a) : "l"(p));
    return a;
}

#define MMA16816(C, A0, A1, A2, A3, B0, B1)                                  \
    asm volatile(                                                            \
        "mma.sync.aligned.m16n8k16.row.col.f32.bf16.bf16.f32 "               \
        "{%0,%1,%2,%3}, {%4,%5,%6,%7}, {%8,%9}, {%0,%1,%2,%3};"              \
        : "+f"((C)[0]), "+f"((C)[1]), "+f"((C)[2]), "+f"((C)[3])             \
        : "r"(A0), "r"(A1), "r"(A2), "r"(A3), "r"(B0), "r"(B1));

#define LDSM4(R0, R1, R2, R3, ADDR)                                          \
    asm volatile("ldmatrix.sync.aligned.m8n8.x4.shared.b16 {%0,%1,%2,%3}, [%4];" \
                 : "=r"(R0), "=r"(R1), "=r"(R2), "=r"(R3) : "r"(ADDR));

// ---- scalar IIR step macros (exact-head path) ----
#define STEP2S(UA, UB, PS)                                                   \
    {                                                                        \
        float firA_ = fmaf(cb2x, u2x, fmaf(cb1x, u1x, cb0x * (UA)));         \
        float xnA_ = fmaf(na0x, x1x, fmaf(na1x, x2x, firA_));                \
        x2x = x1x; x1x = xnA_; u2x = u1x; u1x = (UA);                        \
        float firB_ = fmaf(cb2y, u2y, fmaf(cb1y, u1y, cb0y * (UB)));         \
        float xnB_ = fmaf(na0y, x1y, fmaf(na1y, x2y, firB_));                \
        x2y = x1y; x1y = xnB_; u2y = u1y; u1y = (UB);                        \
        PS = xnA_ + xnB_;                                                    \
    }
#define STEP2N(UA, UB)                                                       \
    {                                                                        \
        float firA_ = fmaf(cb2x, u2x, fmaf(cb1x, u1x, cb0x * (UA)));         \
        float xnA_ = fmaf(na0x, x1x, fmaf(na1x, x2x, firA_));                \
        x2x = x1x; x1x = xnA_; u2x = u1x; u1x = (UA);                        \
        float firB_ = fmaf(cb2y, u2y, fmaf(cb1y, u1y, cb0y * (UB)));         \
        float xnB_ = fmaf(na0y, x1y, fmaf(na1y, x2y, firB_));                \
        x2y = x1y; x1y = xnB_; u2y = u1y; u1y = (UB);                        \
    }

struct __align__(16) FSmem {
    __nv_bfloat16 ahi[AROWS * 8];    // A tile hi split: row j <-> u[t0-15+j]
    __nv_bfloat16 alo[AROWS * 8];
};

__global__ void __launch_bounds__(128) fused_kernel(
    const float* __restrict__ bc, const float* __restrict__ ac,
    const float* __restrict__ u_in, const float* __restrict__ y0,
    const float* __restrict__ u0, float* __restrict__ y)
{
    const int b = blockIdx.y;
    const int bx = blockIdx.x;
    const int tid = threadIdx.x;

    // ================= exact-head block (t = 0..127, exact ICs) ============
    if (bx == 64) {
        const int o = tid & 7, iq = (tid >> 3) & 3, cb = tid >> 5;
        __shared__ __align__(16) float us[4 * 416];   // 4 chunks x 4 planes x 104

        const float* bq = bc + o * 24 + iq * 6;
        const float cb0x = bq[0], cb1x = bq[1], cb2x = bq[2];
        const float cb0y = bq[3], cb1y = bq[4], cb2y = bq[5];
        const float4 av = *(const float4*)(ac + o * 16 + iq * 4);
        const float na0x = -av.x, na1x = -av.y, na0y = -av.z, na1y = -av.w;

        // tile: slot r <-> t = c*32 - 18 + r (50 slots per chunk)
#pragma unroll
        for (int c = 0; c < 4; c++) {
            float* dst = us + c * 416;
            const int lo = (c == 0) ? 36 : 0;
            const float4* src = (const float4*)u_in +
                ((c == 0) ? (size_t)b * Tt * 2 : ((size_t)b * Tt + c * 32 - 18) * 2) - lo;
            if (tid >= lo && tid < 100) {
                const float4 v = src[tid];
                const int ts = tid >> 1, h = tid & 1;
                float* p0 = dst + (2 * h) * 104 + ts * 2;
                p0[0] = v.x; p0[1] = v.y; p0[104] = v.z; p0[105] = v.w;
            }
        }
        if (tid < 16) {
            const int r = 16 + (tid >> 3), ii = tid & 7;
            // u_0[...,k] = u[-1-k]: slot 17 -> u[-1] (k=0), slot 16 -> u[-2] (k=1)
            us[(ii >> 1) * 104 + r * 2 + (ii & 1)] = u0[(b * 8 + ii) * 3 + (17 - r)];
        }
        __syncthreads();

        const float* upq = us + cb * 416 + iq * 104;
        float x1x, x2x, u1x, u2x, x1y, x2y, u1y, u2y;
        if (cb == 0) {
            const float4 v = *(const float4*)(y0 + (b * 8 + o) * 16 + iq * 4);
            x1x = v.x; x2x = v.y; x1y = v.z; x2y = v.w;      // x[-1], x[-2]
            const float4 w = *(const float4*)(upq + 16 * 2); // slots 16,17
            u2x = w.x; u2y = w.y; u1x = w.z; u1y = w.w;      // u[-2], u[-1]
        } else {
            x1x = x2x = x1y = x2y = 0.f;
            const float4 w = *(const float4*)(upq);          // slots 0,1
            u2x = w.x; u2y = w.y; u1x = w.z; u1y = w.w;
#pragma unroll
            for (int r = 2; r < 18; r += 2) {                // 16-step warm-up
                const float4 v = *(const float4*)(upq + r * 2);
                STEP2N(v.x, v.y) STEP2N(v.z, v.w)
            }
        }

        float* yp = y + ((size_t)b * Tt + cb * 32) * 8 + o;
        const bool hi1 = (iq & 2) != 0, hi0 = (iq & 1) != 0;
#pragma unroll
        for (int s = 0; s < 32; s += 4) {
            float ps0, ps1, ps2, ps3;
            const float4 va = *(const float4*)(upq + (18 + s) * 2);
            STEP2S(va.x, va.y, ps0)
            STEP2S(va.z, va.w, ps1)
            const float4 vb = *(const float4*)(upq + (20 + s) * 2);
            STEP2S(vb.x, vb.y, ps2)
            STEP2S(vb.z, vb.w, ps3)
            const float sA0 = hi1 ? ps0 : ps2;
            const float sA1 = hi1 ? ps1 : ps3;
            const float rA0 = __shfl_xor_sync(0xffffffffu, sA0, 16);
            const float rA1 = __shfl_xor_sync(0xffffffffu, sA1, 16);
            const float w0 = (hi1 ? ps2 : ps0) + rA0;
            const float w1 = (hi1 ? ps3 : ps1) + rA1;
            const float sB = hi0 ? w0 : w1;
            const float rB = __shfl_xor_sync(0xffffffffu, sB, 8);
            const float mine = hi0 ? w1 : w0;
            yp[(size_t)(s + iq) * 8] = mine + rB;
        }
        return;
    }

    // ================= GEMM blocks: tiles t_idx = 1 + bx*2 + {0,1} =========
    __shared__ FSmem sm;
    const int wid = tid >> 5, lid = tid & 31;
    const int tc = lid & 3, g = lid >> 2;

    // ---- B fragments in registers: lane (g,tc) runs the tap recurrences
    // for its own two filters fA=(o=g,i=2tc), fB=(o=g,i=2tc+1).
    uint32_t bh0[NS], bh1[NS], bl0[NS], bl1[NS];
    {
        const int fA = g * 8 + 2 * tc, fB = fA + 1;
        const float bA0 = bc[fA * 3 + 0], bA1 = bc[fA * 3 + 1], bA2 = bc[fA * 3 + 2];
        const float bB0 = bc[fB * 3 + 0], bB1 = bc[fB * 3 + 1], bB2 = bc[fB * 3 + 2];
        const float2 aA = *(const float2*)(ac + fA * 2);
        const float2 aB = *(const float2*)(ac + fB * 2);
        float hA1 = 0.f, hA2 = 0.f, hB1 = 0.f, hB2 = 0.f;
#pragma unroll
        for (int d = 0; d < NT; d++) {
            const float fa = (d == 0) ? bA0 : (d == 1) ? bA1 : (d == 2) ? bA2 : 0.f;
            const float fb = (d == 0) ? bB0 : (d == 1) ? bB1 : (d == 2) ? bB2 : 0.f;
            const float hA = fa - aA.x * hA1 - aA.y * hA2;
            const float hB = fb - aB.x * hB1 - aB.y * hB2;
            hA2 = hA1; hA1 = hA; hB2 = hB1; hB1 = hB;
            const __nv_bfloat16 hiA = __float2bfloat16(hA);
            const __nv_bfloat16 hiB = __float2bfloat16(hB);
            const float loAf = hA - __bfloat162float(hiA);
            const float loBf = hB - __bfloat162float(hiB);
            __nv_bfloat162 hp = __halves2bfloat162(hiA, hiB);
            __nv_bfloat162 lp = __halves2bfloat162(__float2bfloat16(loAf),
                                                   __float2bfloat16(loBf));
            if (d & 1) { bh0[d >> 1] = *(uint32_t*)&hp; bl0[d >> 1] = *(uint32_t*)&lp; }
            else       { bh1[d >> 1] = *(uint32_t*)&hp; bl1[d >> 1] = *(uint32_t*)&lp; }
        }
    }

    const uint32_t ahi_u = smem_u32(sm.ahi);
    const uint32_t alo_u = smem_u32(sm.alo);
    // ldmatrix lane address: lanes 0-15 -> rows 0-15 (k 0-7), 16-31 -> +1 row
    const uint32_t rowoff = (uint32_t)(((lid & 15) + (lid >> 4)) * 16);

#pragma unroll
    for (int k = 0; k < 2; k++) {
        const int t_idx = 1 + bx * 2 + k;       // 1..128; 128 masked
        const bool active = (t_idx <= 127);
        if (active) {
            const int t0 = t_idx * 128;
            const float4* src = (const float4*)u_in + ((size_t)b * Tt + t0 - 15) * 2;
            for (int q = tid; q < 143 * 2; q += 128) {
                const float4 v = src[q];
                const __nv_bfloat16 h0 = __float2bfloat16(v.x);
                const __nv_bfloat16 h1 = __float2bfloat16(v.y);
                const __nv_bfloat16 h2 = __float2bfloat16(v.z);
                const __nv_bfloat16 h3 = __float2bfloat16(v.w);
                const __nv_bfloat16 l0 = __float2bfloat16(v.x - __bfloat162float(h0));
                const __nv_bfloat16 l1 = __float2bfloat16(v.y - __bfloat162float(h1));
                const __nv_bfloat16 l2 = __float2bfloat16(v.z - __bfloat162float(h2));
                const __nv_bfloat16 l3 = __float2bfloat16(v.w - __bfloat162float(h3));
                __nv_bfloat162* dh = (__nv_bfloat162*)sm.ahi + q * 2;
                dh[0] = __halves2bfloat162(h0, h1);
                dh[1] = __halves2bfloat162(h2, h3);
                __nv_bfloat162* dl = (__nv_bfloat162*)sm.alo + q * 2;
                dl[0] = __halves2bfloat162(l0, l1);
                dl[1] = __halves2bfloat162(l2, l3);
            }
        }
        __syncthreads();
        if (active) {
            float acc[2][4];
#pragma unroll
            for (int m = 0; m < 2; m++)
#pragma unroll
                for (int e = 0; e < 4; e++) acc[m][e] = 0.f;
#pragma unroll
            for (int s = 0; s < NS; s++) {
#pragma unroll
                for (int m = 0; m < 2; m++) {
                    const int mt = wid * 2 + m;
                    // A_s row t: k0-7 = u[t0+t-2s-1] -> smem row j = t + 14 - 2s
                    const uint32_t base = (uint32_t)((mt * 16 + 14 - 2 * s) * 16) + rowoff;
                    uint32_t ah0, ah1, ah2, ah3, al0r, al1r, al2r, al3r;
                    LDSM4(ah0, ah1, ah2, ah3, ahi_u + base)
                    LDSM4(al0r, al1r, al2r, al3r, alo_u + base)
                    MMA16816(acc[m], ah0, ah1, ah2, ah3, bh0[s], bh1[s])
                    MMA16816(acc[m], al0r, al1r, al2r, al3r, bh0[s], bh1[s])
                    MMA16816(acc[m], ah0, ah1, ah2, ah3, bl0[s], bl1[s])
                }
            }
            const int t0 = t_idx * 128;
#pragma unroll
            for (int m = 0; m < 2; m++) {
                const int mt = wid * 2 + m;
                float* dst = y + ((size_t)b * Tt + t0 + mt * 16 + g) * 8 + 2 * tc;
                *(float2*)dst = make_float2(acc[m][0], acc[m][1]);
                *(float2*)(dst + 64) = make_float2(acc[m][2], acc[m][3]);  // row g+8
            }
        }
        __syncthreads();
    }
}

extern "C" void kernel_launch(void* const* d_in, const int* in_sizes, int n_in,
                              void* d_out, int out_size) {
    const float* bc = (const float*)d_in[0];  // b_coeff (O,I,3)
    const float* ac = (const float*)d_in[1];  // a_coeff (O,I,2)
    const float* u  = (const float*)d_in[2];  // u_in    (B,T,I)
    const float* y0 = (const float*)d_in[3];  // y_0     (B,O,I,2)
    const float* u0 = (const float*)d_in[4];  // u_0     (B,I,3)
    float* y = (float*)d_out;                 // (B,T,O)

    fused_kernel<<<dim3(65, Bb), 128>>>(bc, ac, u, y0, u0, y);
}